// round 9
// baseline (speedup 1.0000x reference)
#include <cuda_runtime.h>
#include <cuda_bf16.h>
#include <cstdint>

// Segment max-pool, scatter-on-store (gather-free reduce):
//   point_features: (B, C, N) float32   [d_in[0]]
//   box_ids_of_pts: (B, N)    int32/int64 (auto-detected)  [d_in[2]]
//   out:            (B*S, C)  float32   S = 100
//
// Grid = (chunks, B, slabs). Per block: counting-sort rank per point once;
// per 2-channel group: LDG.128 into regs (next group prefetched during the
// reduce), scatter-STS into sorted tile, reduce CONTIGUOUS runs with fmaxf,
// one encoded-int atomicMax per (seg, half, ch, block).

#define S_SEG    100
#define CHUNK    2048
#define NTHREADS 256
#define CG       2
#define SLABS    4
#define TILE_PAD 8
#define PPT      (CHUNK / NTHREADS)      // 8 points per thread
#define V4PT     (PPT / 4)               // 2 float4 per thread per channel

__device__ int g_lab_is_64;

__device__ __forceinline__ int enc_f32(float f) {
    int i = __float_as_int(f);
    return (i >= 0) ? i : (i ^ 0x7FFFFFFF);
}

// init output to enc(-inf); block0/thread0 also detects label dtype:
// int64 labels in [0,100) look like [lab,0,lab,0,...] as int32 words.
__global__ void init_out_kernel(int* __restrict__ outI, int n,
                                const int* __restrict__ lab32) {
    int i = blockIdx.x * blockDim.x + threadIdx.x;
    if (i < n) outI[i] = 0x807FFFFF;
    if (blockIdx.x == 0 && threadIdx.x == 0) {
        int is64 = 1;
        #pragma unroll 1
        for (int k = 0; k < 128; k++) {
            int lo = lab32[2 * k], hi = lab32[2 * k + 1];
            if (hi != 0 || lo < 0 || lo >= S_SEG) { is64 = 0; break; }
        }
        g_lab_is_64 = is64;
    }
}

__global__ void decode_out_kernel(float* __restrict__ outF, int n) {
    int i = blockIdx.x * blockDim.x + threadIdx.x;
    if (i < n) {
        int v = __float_as_int(outF[i]);
        outF[i] = __int_as_float((v >= 0) ? v : (v ^ 0x7FFFFFFF));
    }
}

__global__ __launch_bounds__(NTHREADS)
void seg_max_kernel(const float* __restrict__ pf,
                    const int* __restrict__ lab32,
                    int* __restrict__ outI,
                    int C, int N) {
    __shared__ __align__(16) float s_tile[CG][CHUNK + TILE_PAD];
    __shared__ __align__(16) unsigned short s_rank[CHUNK];
    __shared__ __align__(16) unsigned short s_lab[CHUNK];
    __shared__ int s_cnt[S_SEG];
    __shared__ int s_off[S_SEG + 1];
    __shared__ int s_cur[S_SEG + 1];     // [S_SEG] = invalid-overflow cursor

    const int tid = threadIdx.x;
    const int b = blockIdx.y;
    const int chPerSlab = C / SLABS;                 // 32
    const int chBase = blockIdx.z * chPerSlab;
    const int n0 = blockIdx.x * CHUNK;
    const int len = min(CHUNK, N - n0);
    const int is64 = g_lab_is_64;

    for (int s = tid; s < S_SEG; s += NTHREADS) s_cnt[s] = 0;
    __syncthreads();

    // ---- labels + histogram (dtype-agnostic) ----
    {
        const size_t base = (size_t)b * N + n0;
        for (int i = tid; i < len; i += NTHREADS) {
            long long l;
            if (is64) {
                int2 w = ((const int2*)lab32)[base + i];
                l = ((long long)w.y << 32) | (unsigned int)w.x;
            } else {
                l = lab32[base + i];
            }
            if (l >= 0 && l < S_SEG) {
                s_lab[i] = (unsigned short)l;
                atomicAdd(&s_cnt[(int)l], 1);
            } else {
                s_lab[i] = 0xFFFF;
            }
        }
    }
    __syncthreads();

    if (tid == 0) {
        int run = 0;
        #pragma unroll 4
        for (int s = 0; s < S_SEG; s++) { s_off[s] = run; run += s_cnt[s]; }
        s_off[S_SEG] = run;
        s_cur[S_SEG] = run;              // invalids parked after valid range
    }
    __syncthreads();
    for (int s = tid; s < S_SEG; s += NTHREADS) s_cur[s] = s_off[s];
    __syncthreads();

    // ---- rank of each point in label-sorted order ----
    for (int i = tid; i < len; i += NTHREADS) {
        unsigned short l = s_lab[i];
        int bin = (l == 0xFFFF) ? S_SEG : (int)l;
        int pos = atomicAdd(&s_cur[bin], 1);
        s_rank[i] = (unsigned short)pos;
    }
    __syncthreads();

    // ---- channel groups, register-prefetched ----
    const int nGroups = chPerSlab / CG;              // 16
    float4 r[CG][V4PT];

    auto ldg_group = [&](int g) {
        const int ch0 = chBase + g * CG;
        #pragma unroll
        for (int cl = 0; cl < CG; cl++) {
            const float4* src4 = (const float4*)
                (pf + (((size_t)b * C + ch0 + cl) * N + n0));
            #pragma unroll
            for (int v = 0; v < V4PT; v++) {
                const int f4 = tid + v * NTHREADS;   // float4 index
                if (f4 * 4 < len) r[cl][v] = src4[f4];
            }
        }
    };

    ldg_group(0);

    for (int g = 0; g < nGroups; g++) {
        __syncthreads();   // previous reduce done before tile overwrite

        // scatter registers into sorted tile
        #pragma unroll
        for (int v = 0; v < V4PT; v++) {
            const int i = (tid + v * NTHREADS) * 4;
            if (i + 3 < len) {
                ushort4 rk = ((const ushort4*)s_rank)[tid + v * NTHREADS];
                #pragma unroll
                for (int cl = 0; cl < CG; cl++) {
                    s_tile[cl][rk.x] = r[cl][v].x;
                    s_tile[cl][rk.y] = r[cl][v].y;
                    s_tile[cl][rk.z] = r[cl][v].z;
                    s_tile[cl][rk.w] = r[cl][v].w;
                }
            } else if (i < len) {                    // ragged tail
                for (int j = 0; j < 4 && i + j < len; j++) {
                    #pragma unroll
                    for (int cl = 0; cl < CG; cl++)
                        s_tile[cl][s_rank[i + j]] =
                            ((const float*)&r[cl][v])[j];
                }
            }
        }

        if (g + 1 < nGroups) ldg_group(g + 1);       // hide DRAM under reduce
        __syncthreads();

        // reduce contiguous runs: task = (seg, half, channel-in-group)
        const int ch0 = chBase + g * CG;
        for (int task = tid; task < S_SEG * 2 * CG; task += NTHREADS) {
            const int seg = task >> 2;
            const int sub = task & 3;
            const int cl = sub & 1;
            const int half = sub >> 1;
            const int q0 = s_off[seg];
            const int q1 = s_off[seg + 1];
            const int mid = (q0 + q1 + 1) >> 1;
            const int p0 = half ? mid : q0;
            const int p1 = half ? q1 : mid;
            if (p0 < p1) {
                float m = -__int_as_float(0x7F800000);
                const float* row = &s_tile[cl][0];
                #pragma unroll 4
                for (int p = p0; p < p1; p++)
                    m = fmaxf(m, row[p]);
                atomicMax(&outI[((size_t)(b * S_SEG + seg)) * C + ch0 + cl],
                          enc_f32(m));
            }
        }
    }
}

extern "C" void kernel_launch(void* const* d_in, const int* in_sizes, int n_in,
                              void* d_out, int out_size) {
    const float* pf = (const float*)d_in[0];
    const int* lab32 = (const int*)d_in[2];

    const int pf_elems = in_sizes[0];      // B*C*N
    const int lab_elems = in_sizes[2];     // B*N
    const int C = pf_elems / lab_elems;    // 128
    const int B = out_size / (S_SEG * C);  // 8
    const int N = lab_elems / B;           // 65536

    int* outI = (int*)d_out;
    float* outF = (float*)d_out;

    const int initBlocks = (out_size + 255) / 256;
    init_out_kernel<<<initBlocks, 256>>>(outI, out_size, lab32);

    const int numChunks = (N + CHUNK - 1) / CHUNK;
    dim3 grid(numChunks, B, SLABS);
    seg_max_kernel<<<grid, NTHREADS>>>(pf, lab32, outI, C, N);

    decode_out_kernel<<<initBlocks, 256>>>(outF, out_size);
}